// round 13
// baseline (speedup 1.0000x reference)
#include <cuda_runtime.h>
#include <math.h>

#define BB 8
#define SS 1024
#define DD 256
#define HH 32
#define INF 64
#define LL 4

#define MN 2560                // magnitude table entries (bit-grid)
#define MBASE (76u << 23)      // float bits of 2^-51; 32 steps/octave
#define MSH 18
#define MMASK ((1u << MSH) - 1u)
#define PHN 1024               // phase table entries

typedef unsigned long long u64;

// scratch: z interleaved (r,i) in [B][D][S]; zout = real part after layers
__device__ float2 g_zri[BB*DD*SS];
__device__ float  g_zout[BB*DD*SS];
// lookup tables
__device__ float  g_magtab[LL][MN];      // E = exp(scale*delta), m2-bit grid
__device__ float2 g_phtab[LL][PHN];      // NORMALIZED pv_out(u)

__device__ __forceinline__ float gelu_exact(float v){
    return 0.5f * v * (1.0f + erff(v * 0.70710678118654752f));
}

// ---- f32x2 packed helpers (sm_100+) ----
__device__ __forceinline__ u64 pk2(float lo, float hi){
    u64 r; asm("mov.b64 %0, {%1, %2};" : "=l"(r) : "f"(lo), "f"(hi)); return r;
}
__device__ __forceinline__ void upk2(u64 v, float &lo, float &hi){
    asm("mov.b64 {%0, %1}, %2;" : "=f"(lo), "=f"(hi) : "l"(v));
}
__device__ __forceinline__ u64 fma2(u64 a, u64 b, u64 c){
    u64 r; asm("fma.rn.f32x2 %0, %1, %2, %3;" : "=l"(r) : "l"(a), "l"(b), "l"(c)); return r;
}
__device__ __forceinline__ u64 mul2(u64 a, u64 b){
    u64 r; asm("mul.rn.f32x2 %0, %1, %2;" : "=l"(r) : "l"(a), "l"(b)); return r;
}
__device__ __forceinline__ u64 add2(u64 a, u64 b){
    u64 r; asm("add.rn.f32x2 %0, %1, %2;" : "=l"(r) : "l"(a), "l"(b)); return r;
}
__device__ __forceinline__ float rcp_ap(float x){
    float y; asm("rcp.approx.f32 %0, %1;" : "=f"(y) : "f"(x)); return y;
}
__device__ __forceinline__ float rsqrt_ap(float x){
    float y; asm("rsqrt.approx.f32 %0, %1;" : "=f"(y) : "f"(x)); return y;
}

// ---------------------------------------------------------------------------
// Fused Kernel A+T: blocks [0,512) do embed; rest build tables.
// Embed: thread owns d-pair (2t', 2t'+1) x 8 s; weights load as u64 pairs.
// ---------------------------------------------------------------------------
#define TS 16
#define XST2 18                           // u64 row stride (16B aligned)
#define EMB_BLOCKS (BB*(SS/TS))          // 512
#define TAB_BLOCKS (LL*(MN+PHN)/8)       // 1792

__global__ void __launch_bounds__(256) embed_tables_kernel(
    const float* __restrict__ x,
    const float* __restrict__ erw, const float* __restrict__ erb,
    const float* __restrict__ eiw, const float* __restrict__ eib,
    const float* __restrict__ pm_w1, const float* __restrict__ pm_b1,
    const float* __restrict__ pm_w2, const float* __restrict__ pm_b2,
    const float* __restrict__ pp_w1, const float* __restrict__ pp_b1,
    const float* __restrict__ pp_w2, const float* __restrict__ pp_b2,
    const float* __restrict__ mag_scale)
{
    if (blockIdx.x >= EMB_BLOCKS){
        // ---------------- table builder: warp per entry, lane = hidden j ----
        int wgid = (blockIdx.x - EMB_BLOCKS) * 8 + (threadIdx.x >> 5);
        int j    = threadIdx.x & 31;
        if (wgid < LL*MN){
            int l = wgid / MN, k = wgid % MN;
            unsigned bits = MBASE + ((unsigned)k << MSH);
            float m2 = __uint_as_float(bits);
            float lm = 0.5f * logf(m2);
            float h  = fmaf(pm_w1[l*HH+j], lm, pm_b1[l*HH+j]);
            float v  = gelu_exact(h) * pm_w2[l*HH+j];
            #pragma unroll
            for (int o = 16; o; o >>= 1) v += __shfl_down_sync(0xffffffffu, v, o);
            if (j == 0) g_magtab[l][k] = expf(mag_scale[l] * (v + pm_b2[l]));
            return;
        }
        wgid -= LL*MN;
        {
            int l = wgid / PHN, k = wgid % PHN;
            float uu = 4.0f * (float)k / (float)PHN;
            float xx, yy;
            if (uu < 1.f)      { xx = 1.f-uu; yy = uu;     }
            else if (uu < 2.f) { xx = 1.f-uu; yy = 2.f-uu; }
            else if (uu < 3.f) { xx = uu-3.f; yy = 2.f-uu; }
            else               { xx = uu-3.f; yy = uu-4.f; }
            float inv = rsqrtf(fmaf(xx,xx,yy*yy));
            float px = xx*inv, py = yy*inv;
            float h = fmaf(px, pp_w1[l*2*HH + j],
                      fmaf(py, pp_w1[l*2*HH + HH + j], pp_b1[l*HH+j]));
            float g = gelu_exact(h);
            float vr = g * pp_w2[(l*HH+j)*2];
            float vi = g * pp_w2[(l*HH+j)*2 + 1];
            #pragma unroll
            for (int o = 16; o; o >>= 1){
                vr += __shfl_down_sync(0xffffffffu, vr, o);
                vi += __shfl_down_sync(0xffffffffu, vi, o);
            }
            if (j == 0){
                vr += pp_b2[l*2]; vi += pp_b2[l*2+1];
                float n = sqrtf(fmaf(vr, vr, vi*vi));
                float innv = 1.0f / fmaxf(n, 1e-12f);
                g_phtab[l][k] = make_float2(vr*innv, vi*innv);   // normalized
            }
            return;
        }
    }

    // -------------------------------- embed ---------------------------------
    __shared__ u64   xsh2[INF*XST2];      // duplicated (x,x) pairs, [i][s]
    __shared__ float zshr[DD][TS+1];
    __shared__ float zshi[DD][TS+1];

    int t   = threadIdx.x;
    int sub = t >> 7;                     // s-half: 0 -> s 0..7, 1 -> s 8..15
    int tt  = t & 127;
    int d0  = 2*tt;                       // d-pair (d0, d0+1)
    int nb_per_b = SS / TS;               // 64
    int b  = blockIdx.x / nb_per_b;
    int s0 = (blockIdx.x % nb_per_b) * TS;

    const float* xp = x + (size_t)(b*SS + s0) * INF;
    for (int e = t; e < TS*INF; e += 256){
        int s = e >> 6, i = e & 63;
        float v = xp[e];
        xsh2[i*XST2 + s] = pk2(v, v);
    }
    __syncthreads();

    // bias init, packed over (d0, d0+1)
    u64 br2 = *(const u64*)(erb + d0);
    u64 bi2 = *(const u64*)(eib + d0);
    u64 zr2[8], zi2[8];
    #pragma unroll
    for (int s = 0; s < 8; s++){ zr2[s] = br2; zi2[s] = bi2; }

    #pragma unroll 8
    for (int i = 0; i < INF; i++){
        u64 wr2 = *(const u64*)(erw + i*DD + d0);   // LDG.64 = both d weights
        u64 wi2 = *(const u64*)(eiw + i*DD + d0);
        const ulonglong2* xr = (const ulonglong2*)(xsh2 + i*XST2) + sub*4;
        #pragma unroll
        for (int q = 0; q < 4; q++){
            ulonglong2 xv = xr[q];                  // 2 duplicated s values
            zr2[2*q]   = fma2(xv.x, wr2, zr2[2*q]);
            zi2[2*q]   = fma2(xv.x, wi2, zi2[2*q]);
            zr2[2*q+1] = fma2(xv.y, wr2, zr2[2*q+1]);
            zi2[2*q+1] = fma2(xv.y, wi2, zi2[2*q+1]);
        }
    }

    // rotation packed over the d-pair
    const float NEGC = -9.210340371976184f/256.0f;
    float f0 = expf((float)d0 * NEGC);
    float f1 = expf((float)(d0+1) * NEGC);
    int s_start = s0 + sub*8;
    float sn0, cs0, sn1, cs1, sd0, cd0, sd1, cd1;
    sincosf((float)s_start * f0, &sn0, &cs0);
    sincosf((float)s_start * f1, &sn1, &cs1);
    sincosf(f0, &sd0, &cd0);
    sincosf(f1, &sd1, &cd1);
    u64 cs2 = pk2(cs0, cs1), sn2 = pk2(sn0, sn1);
    u64 cd2 = pk2(cd0, cd1), sd2 = pk2(sd0, sd1);
    u64 nsn2 = pk2(-sn0, -sn1), nsd2 = pk2(-sd0, -sd1);

    #pragma unroll
    for (int s = 0; s < 8; s++){
        u64 rr = fma2(zr2[s], cs2, mul2(zi2[s], nsn2));  // r*c - i*s
        u64 ii = fma2(zr2[s], sn2, mul2(zi2[s], cs2));   // r*s + i*c
        float r0, r1, i0, i1;
        upk2(rr, r0, r1); upk2(ii, i0, i1);
        int sl = sub*8 + s;
        zshr[d0][sl]   = r0; zshi[d0][sl]   = i0;
        zshr[d0+1][sl] = r1; zshi[d0+1][sl] = i1;
        u64 cn = fma2(cs2, cd2, mul2(sn2, nsd2));        // advance angle
        u64 sx = fma2(sn2, cd2, mul2(cs2, sd2));
        cs2 = cn; sn2 = sx;
        nsn2 = mul2(sn2, pk2(-1.f, -1.f));
    }
    __syncthreads();

    // coalesced writeout: warp writes contiguous s-runs
    float2* outz = g_zri + (size_t)b * DD * SS;
    for (int idx = t; idx < DD*TS; idx += 256){
        int dd = idx >> 4;
        int sx = idx & (TS-1);
        outz[dd*SS + s0 + sx] = make_float2(zshr[dd][sx], zshi[dd][sx]);
    }
}

// ---------------------------------------------------------------------------
// Kernel B: 4 causal polarizing blocks. 128 threads x 8 elems, (r,i) packed
// as f32x2. Bit-indexed E-table kills log+exp (2 MUFU/elem).
// ---------------------------------------------------------------------------
#define NT 128
__global__ void __launch_bounds__(NT) layers_kernel()
{
    __shared__ u64 warp_s[LL][4];

    int t = threadIdx.x;
    size_t base = (size_t)blockIdx.x * SS;        // blockIdx = b*D + d
    const ulonglong2* zp = (const ulonglong2*)(g_zri + base);
    ulonglong2 p0 = zp[4*t+0], p1 = zp[4*t+1], p2 = zp[4*t+2], p3 = zp[4*t+3];
    u64 z[8] = { p0.x, p0.y, p1.x, p1.y, p2.x, p2.y, p3.x, p3.y };

    float invc[8];
    #pragma unroll
    for (int k = 0; k < 8; k++) invc[k] = 1.0f / (float)(t*8 + k + 1);

    int lane = t & 31, wid = t >> 5;
    const u64 NEG1 = pk2(-1.0f, -1.0f);

    #pragma unroll
    for (int l = 0; l < LL; l++){
        // ---- packed inclusive scan over 1024 (r,i) pairs ----
        u64 c[8];
        c[0] = z[0];
        #pragma unroll
        for (int k = 1; k < 8; k++) c[k] = add2(c[k-1], z[k]);
        u64 w = c[7];
        #pragma unroll
        for (int o = 1; o < 32; o <<= 1){
            u64 u = __shfl_up_sync(0xffffffffu, w, o);
            if (lane >= o) w = add2(w, u);
        }
        if (lane == 31) warp_s[l][wid] = w;
        __syncthreads();                  // per-layer buffer: single barrier
        u64 off = 0ull;
        #pragma unroll
        for (int w2 = 0; w2 < 3; w2++){
            if (w2 < wid) off = add2(off, warp_s[l][w2]);
        }
        u64 bse = add2(off, fma2(c[7], NEG1, w));   // exclusive base

        #pragma unroll
        for (int k = 0; k < 8; k++){
            u64 cum = add2(bse, c[k]);
            float R, I; upk2(cum, R, I);
            float Ar = R*invc[k], Ai = I*invc[k];
            float m2 = fmaf(Ar, Ar, Ai*Ai) + 1e-12f;

            // E-table: bit-grid index (piecewise-log2), lerp exact in value
            unsigned bb = __float_as_uint(m2);
            int idx = (int)((bb - MBASE) >> MSH);
            idx = min(idx, MN-2);
            float fr = (float)(bb & MMASK) * (1.0f/262144.0f);
            float E0 = __ldg(&g_magtab[l][idx]);
            float E1 = __ldg(&g_magtab[l][idx+1]);
            float E  = fmaf(fr, E1 - E0, E0);

            // diamond angle u in [0,4)
            float ax = fabsf(Ar), ay = fabsf(Ai);
            float q  = ay * rcp_ap(ax + ay + 1e-30f);
            float u  = (Ar >= 0.f) ? q : 2.f - q;
            u        = (Ai >= 0.f) ? u : 4.f - u;
            float pf = u * ((float)PHN * 0.25f);
            float fl = floorf(pf);
            int   pp0 = ((int)fl) & (PHN-1);
            int   pp1 = (pp0 + 1)  & (PHN-1);
            float prf = pf - fl;
            // packed lerp of the normalized (gr,gi) table entries
            u64 gA = __ldg((const u64*)&g_phtab[l][pp0]);
            u64 gB = __ldg((const u64*)&g_phtab[l][pp1]);
            u64 gD = fma2(gA, NEG1, gB);               // gB - gA
            u64 g2 = fma2(pk2(prf, prf), gD, gA);

            float r = m2 * rsqrt_ap(m2) * E;           // sqrt(m2)*E
            z[k] = fma2(pk2(r, r), g2, z[k]);
        }
    }

    // decode needs only the real part
    float zr[8], zi_dummy;
    #pragma unroll
    for (int k = 0; k < 8; k++) upk2(z[k], zr[k], zi_dummy);
    float4* outp = (float4*)(g_zout + base);
    outp[2*t]   = make_float4(zr[0], zr[1], zr[2], zr[3]);
    outp[2*t+1] = make_float4(zr[4], zr[5], zr[6], zr[7]);
}

// ---------------------------------------------------------------------------
// Kernel C: decode as warp-tiled GEMV. Block = 32 s-values, 256 threads.
// ---------------------------------------------------------------------------
#define DBS 32
__global__ void __launch_bounds__(256) decode_kernel(
    const float* __restrict__ w1, const float* __restrict__ b1,
    const float* __restrict__ w2, const float* __restrict__ b2,
    float* __restrict__ out)
{
    __shared__ float sbuf[DD*HH];   // 32 KB: w1 tile [d][h], later partials [8][DBS][HH]
    int t = threadIdx.x;
    int w = t >> 5, lane = t & 31;
    int si = lane & 7;                   // s-quad: s = s_base + si*4 .. +3
    int hq = lane >> 3;                  // h-oct:  h = hq*8 .. +7

    int s_base = blockIdx.x * DBS;
    int b = s_base >> 10, s_in = s_base & (SS-1);
    const float* fp = g_zout + (size_t)b * DD * SS + (size_t)(w*32) * SS
                      + s_in + si*4;

    // prefetch first f chunk (4 d), then preload w1 (overlaps)
    float4 fbuf[2][4];
    #pragma unroll
    for (int dd = 0; dd < 4; dd++)
        fbuf[0][dd] = *(const float4*)(fp + (size_t)dd * SS);

    const float4* w1v = (const float4*)w1;
    float4* sv = (float4*)sbuf;
    #pragma unroll
    for (int i = 0; i < DD*HH/4/256; i++) sv[t + i*256] = w1v[t + i*256];
    __syncthreads();

    u64 acc[16];                         // [s-quad 4][h-pair 4]
    #pragma unroll
    for (int h = 0; h < 16; h++) acc[h] = 0ull;

    #pragma unroll
    for (int ch = 0; ch < 8; ch++){
        if (ch < 7){
            #pragma unroll
            for (int dd = 0; dd < 4; dd++)
                fbuf[(ch+1)&1][dd] = *(const float4*)(fp + (size_t)((ch+1)*4+dd) * SS);
        }
        #pragma unroll
        for (int dd = 0; dd < 4; dd++){
            int d = ch*4 + dd;
            const float* wr = sbuf + (w*32 + d)*HH + hq*8;
            ulonglong2 wv0 = *(const ulonglong2*)(wr);       // h-pairs 0,1
            ulonglong2 wv1 = *(const ulonglong2*)(wr + 4);   // h-pairs 2,3
            float4 f4 = fbuf[ch&1][dd];
            u64 f0 = pk2(f4.x, f4.x), f1 = pk2(f4.y, f4.y);
            u64 f2_ = pk2(f4.z, f4.z), f3 = pk2(f4.w, f4.w);
            acc[0]  = fma2(f0, wv0.x, acc[0]);  acc[1]  = fma2(f0, wv0.y, acc[1]);
            acc[2]  = fma2(f0, wv1.x, acc[2]);  acc[3]  = fma2(f0, wv1.y, acc[3]);
            acc[4]  = fma2(f1, wv0.x, acc[4]);  acc[5]  = fma2(f1, wv0.y, acc[5]);
            acc[6]  = fma2(f1, wv1.x, acc[6]);  acc[7]  = fma2(f1, wv1.y, acc[7]);
            acc[8]  = fma2(f2_, wv0.x, acc[8]); acc[9]  = fma2(f2_, wv0.y, acc[9]);
            acc[10] = fma2(f2_, wv1.x, acc[10]);acc[11] = fma2(f2_, wv1.y, acc[11]);
            acc[12] = fma2(f3, wv0.x, acc[12]); acc[13] = fma2(f3, wv0.y, acc[13]);
            acc[14] = fma2(f3, wv1.x, acc[14]); acc[15] = fma2(f3, wv1.y, acc[15]);
        }
    }
    __syncthreads();   // done reading w1 tile; sbuf becomes partials [8][DBS][HH]

    #pragma unroll
    for (int s4 = 0; s4 < 4; s4++){
        float* pr = sbuf + (w*DBS + si*4 + s4)*HH + hq*8;
        *(ulonglong2*)(pr)     = make_ulonglong2(acc[s4*4+0], acc[s4*4+1]);
        *(ulonglong2*)(pr + 4) = make_ulonglong2(acc[s4*4+2], acc[s4*4+3]);
    }
    __syncthreads();

    // final: warp w handles 4 s-values; lane = hidden unit
    float bb1 = b1[lane], ww2 = w2[lane], bb2 = b2[0];
    #pragma unroll
    for (int si2 = w*4; si2 < w*4 + 4; si2++){
        float hsum = bb1;
        #pragma unroll
        for (int g = 0; g < 8; g++)
            hsum += sbuf[(g*DBS + si2)*HH + lane];
        float y = gelu_exact(hsum) * ww2;
        #pragma unroll
        for (int o = 16; o; o >>= 1) y += __shfl_down_sync(0xffffffffu, y, o);
        if (lane == 0) out[blockIdx.x * DBS + si2] = y + bb2;
    }
}

// ---------------------------------------------------------------------------
extern "C" void kernel_launch(void* const* d_in, const int* in_sizes, int n_in,
                              void* d_out, int out_size)
{
    const float* x     = (const float*)d_in[0];
    const float* er_w  = (const float*)d_in[1];
    const float* er_b  = (const float*)d_in[2];
    const float* ei_w  = (const float*)d_in[3];
    const float* ei_b  = (const float*)d_in[4];
    const float* pm_w1 = (const float*)d_in[5];
    const float* pm_b1 = (const float*)d_in[6];
    const float* pm_w2 = (const float*)d_in[7];
    const float* pm_b2 = (const float*)d_in[8];
    const float* pp_w1 = (const float*)d_in[9];
    const float* pp_b1 = (const float*)d_in[10];
    const float* pp_w2 = (const float*)d_in[11];
    const float* pp_b2 = (const float*)d_in[12];
    const float* mscal = (const float*)d_in[13];
    const float* op_w1 = (const float*)d_in[14];
    const float* op_b1 = (const float*)d_in[15];
    const float* op_w2 = (const float*)d_in[16];
    const float* op_b2 = (const float*)d_in[17];
    float* out = (float*)d_out;

    embed_tables_kernel<<<EMB_BLOCKS + TAB_BLOCKS, 256>>>(
        x, er_w, er_b, ei_w, ei_b,
        pm_w1, pm_b1, pm_w2, pm_b2, pp_w1, pp_b1, pp_w2, pp_b2, mscal);
    layers_kernel<<<BB*DD, NT>>>();
    decode_kernel<<<BB*SS/DBS, 256>>>(op_w1, op_b1, op_w2, op_b2, out);
}

// round 14
// speedup vs baseline: 1.0446x; 1.0446x over previous
#include <cuda_runtime.h>
#include <math.h>

#define BB 8
#define SS 1024
#define DD 256
#define HH 32
#define INF 64
#define LL 4

#define MN 2560                // magnitude table entries (bit-grid)
#define MBASE (76u << 23)      // float bits of 2^-51; 32 steps/octave
#define MSH 18
#define MMASK ((1u << MSH) - 1u)
#define PHN 1024               // phase table entries

typedef unsigned long long u64;

// scratch: z interleaved (r,i) in [B][D][S]; zout = real part after layers
__device__ float2 g_zri[BB*DD*SS];
__device__ float  g_zout[BB*DD*SS];
// lookup tables
__device__ float  g_magtab[LL][MN];      // E = exp(scale*delta), m2-bit grid
__device__ float2 g_phtab[LL][PHN];      // NORMALIZED pv_out(u)

__device__ __forceinline__ float gelu_exact(float v){
    return 0.5f * v * (1.0f + erff(v * 0.70710678118654752f));
}

// ---- f32x2 packed helpers (sm_100+) ----
__device__ __forceinline__ u64 pk2(float lo, float hi){
    u64 r; asm("mov.b64 %0, {%1, %2};" : "=l"(r) : "f"(lo), "f"(hi)); return r;
}
__device__ __forceinline__ void upk2(u64 v, float &lo, float &hi){
    asm("mov.b64 {%0, %1}, %2;" : "=f"(lo), "=f"(hi) : "l"(v));
}
__device__ __forceinline__ u64 fma2(u64 a, u64 b, u64 c){
    u64 r; asm("fma.rn.f32x2 %0, %1, %2, %3;" : "=l"(r) : "l"(a), "l"(b), "l"(c)); return r;
}
__device__ __forceinline__ u64 add2(u64 a, u64 b){
    u64 r; asm("add.rn.f32x2 %0, %1, %2;" : "=l"(r) : "l"(a), "l"(b)); return r;
}
__device__ __forceinline__ float rcp_ap(float x){
    float y; asm("rcp.approx.f32 %0, %1;" : "=f"(y) : "f"(x)); return y;
}
__device__ __forceinline__ float rsqrt_ap(float x){
    float y; asm("rsqrt.approx.f32 %0, %1;" : "=f"(y) : "f"(x)); return y;
}

// ---------------------------------------------------------------------------
// Fused Kernel A+T: blocks [0,512) do embed; rest build tables.
// ---------------------------------------------------------------------------
#define TS 16
#define XST 20
#define EMB_BLOCKS (BB*(SS/TS))          // 512
#define TAB_BLOCKS (LL*(MN+PHN)/8)       // 1792

__global__ void __launch_bounds__(256) embed_tables_kernel(
    const float* __restrict__ x,
    const float* __restrict__ erw, const float* __restrict__ erb,
    const float* __restrict__ eiw, const float* __restrict__ eib,
    const float* __restrict__ pm_w1, const float* __restrict__ pm_b1,
    const float* __restrict__ pm_w2, const float* __restrict__ pm_b2,
    const float* __restrict__ pp_w1, const float* __restrict__ pp_b1,
    const float* __restrict__ pp_w2, const float* __restrict__ pp_b2,
    const float* __restrict__ mag_scale)
{
    if (blockIdx.x >= EMB_BLOCKS){
        // ---------------- table builder: warp per entry, lane = hidden j ----
        int wgid = (blockIdx.x - EMB_BLOCKS) * 8 + (threadIdx.x >> 5);
        int j    = threadIdx.x & 31;
        if (wgid < LL*MN){
            int l = wgid / MN, k = wgid % MN;
            unsigned bits = MBASE + ((unsigned)k << MSH);
            float m2 = __uint_as_float(bits);
            float lm = 0.5f * logf(m2);
            float h  = fmaf(pm_w1[l*HH+j], lm, pm_b1[l*HH+j]);
            float v  = gelu_exact(h) * pm_w2[l*HH+j];
            #pragma unroll
            for (int o = 16; o; o >>= 1) v += __shfl_down_sync(0xffffffffu, v, o);
            if (j == 0) g_magtab[l][k] = expf(mag_scale[l] * (v + pm_b2[l]));
            return;
        }
        wgid -= LL*MN;
        {
            int l = wgid / PHN, k = wgid % PHN;
            float uu = 4.0f * (float)k / (float)PHN;
            float xx, yy;
            if (uu < 1.f)      { xx = 1.f-uu; yy = uu;     }
            else if (uu < 2.f) { xx = 1.f-uu; yy = 2.f-uu; }
            else if (uu < 3.f) { xx = uu-3.f; yy = 2.f-uu; }
            else               { xx = uu-3.f; yy = uu-4.f; }
            float inv = rsqrtf(fmaf(xx,xx,yy*yy));
            float px = xx*inv, py = yy*inv;
            float h = fmaf(px, pp_w1[l*2*HH + j],
                      fmaf(py, pp_w1[l*2*HH + HH + j], pp_b1[l*HH+j]));
            float g = gelu_exact(h);
            float vr = g * pp_w2[(l*HH+j)*2];
            float vi = g * pp_w2[(l*HH+j)*2 + 1];
            #pragma unroll
            for (int o = 16; o; o >>= 1){
                vr += __shfl_down_sync(0xffffffffu, vr, o);
                vi += __shfl_down_sync(0xffffffffu, vi, o);
            }
            if (j == 0){
                vr += pp_b2[l*2]; vi += pp_b2[l*2+1];
                float n = sqrtf(fmaf(vr, vr, vi*vi));
                float innv = 1.0f / fmaxf(n, 1e-12f);
                g_phtab[l][k] = make_float2(vr*innv, vi*innv);   // normalized
            }
            return;
        }
    }

    // -------------------------------- embed ---------------------------------
    __shared__ float  xsh[INF*XST];       // [i][s], stride 20 (16B aligned rows)
    __shared__ float2 zsh[DD][TS+1];      // interleaved (r,i), padded rows

    int t = threadIdx.x;                  // thread t owns d = t
    int nb_per_b = SS / TS;               // 64
    int b  = blockIdx.x / nb_per_b;
    int s0 = (blockIdx.x % nb_per_b) * TS;

    const float* xp = x + (size_t)(b*SS + s0) * INF;
    for (int e = t; e < TS*INF; e += 256){
        int s = e >> 6, i = e & 63;
        xsh[i*XST + s] = xp[e];
    }
    __syncthreads();

    int d = t;
    float br = erb[d], bi = eib[d];
    u64 ar2[TS/2], ai2[TS/2];
    #pragma unroll
    for (int p = 0; p < TS/2; p++){ ar2[p] = pk2(br, br); ai2[p] = pk2(bi, bi); }

    // chunked weight batching: 8 chunks x 8 i; 16 independent LDGs up front
    for (int c = 0; c < 8; c++){
        float wrb[8], wib[8];
        #pragma unroll
        for (int i = 0; i < 8; i++){
            wrb[i] = erw[(c*8+i)*DD + d];
            wib[i] = eiw[(c*8+i)*DD + d];
        }
        #pragma unroll
        for (int i = 0; i < 8; i++){
            u64 wr2 = pk2(wrb[i], wrb[i]);
            u64 wi2 = pk2(wib[i], wib[i]);
            const ulonglong2* xr = (const ulonglong2*)(xsh + (c*8+i)*XST);
            #pragma unroll
            for (int q = 0; q < TS/4; q++){
                ulonglong2 xv = xr[q];         // broadcast LDS.128 = 2 s-pairs
                ar2[2*q]   = fma2(xv.x, wr2, ar2[2*q]);
                ai2[2*q]   = fma2(xv.x, wi2, ai2[2*q]);
                ar2[2*q+1] = fma2(xv.y, wr2, ar2[2*q+1]);
                ai2[2*q+1] = fma2(xv.y, wi2, ai2[2*q+1]);
            }
        }
    }

    // fp32 freq (no FP64 pipe)
    float freq = expf((float)d * (-9.210340371976184f / 256.0f));
    float sn, cs, sdl, cdl;
    sincosf((float)s0 * freq, &sn, &cs);
    sincosf(freq, &sdl, &cdl);
    #pragma unroll
    for (int p = 0; p < TS/2; p++){
        float a0, a1, q0, q1;
        upk2(ar2[p], a0, a1);
        upk2(ai2[p], q0, q1);
        zsh[d][2*p]   = make_float2(a0*cs - q0*sn, a0*sn + q0*cs);
        float cn = cs*cdl - sn*sdl;
        float sx = sn*cdl + cs*sdl;
        cs = cn; sn = sx;
        zsh[d][2*p+1] = make_float2(a1*cs - q1*sn, a1*sn + q1*cs);
        cn = cs*cdl - sn*sdl;
        sx = sn*cdl + cs*sdl;
        cs = cn; sn = sx;
    }
    __syncthreads();

    // coalesced writeout via staging: warp writes contiguous s-runs
    float2* outz = g_zri + (size_t)b * DD * SS;
    for (int idx = t; idx < DD*TS; idx += 256){
        int dd = idx >> 4;
        int sx = idx & (TS-1);
        outz[dd*SS + s0 + sx] = zsh[dd][sx];
    }
}

// ---------------------------------------------------------------------------
// Kernel B: 4 causal polarizing blocks. 128 threads x 8 elems, (r,i) packed
// as f32x2. Bit-indexed E-table kills log+exp (2 MUFU/elem).
// ---------------------------------------------------------------------------
#define NT 128
__global__ void __launch_bounds__(NT) layers_kernel()
{
    __shared__ u64 warp_s[LL][4];

    int t = threadIdx.x;
    size_t base = (size_t)blockIdx.x * SS;        // blockIdx = b*D + d
    const ulonglong2* zp = (const ulonglong2*)(g_zri + base);
    ulonglong2 p0 = zp[4*t+0], p1 = zp[4*t+1], p2 = zp[4*t+2], p3 = zp[4*t+3];
    u64 z[8] = { p0.x, p0.y, p1.x, p1.y, p2.x, p2.y, p3.x, p3.y };

    float invc[8];
    #pragma unroll
    for (int k = 0; k < 8; k++) invc[k] = 1.0f / (float)(t*8 + k + 1);

    int lane = t & 31, wid = t >> 5;
    const u64 NEG1 = pk2(-1.0f, -1.0f);

    #pragma unroll
    for (int l = 0; l < LL; l++){
        // ---- packed inclusive scan over 1024 (r,i) pairs ----
        u64 c[8];
        c[0] = z[0];
        #pragma unroll
        for (int k = 1; k < 8; k++) c[k] = add2(c[k-1], z[k]);
        u64 w = c[7];
        #pragma unroll
        for (int o = 1; o < 32; o <<= 1){
            u64 u = __shfl_up_sync(0xffffffffu, w, o);
            if (lane >= o) w = add2(w, u);
        }
        if (lane == 31) warp_s[l][wid] = w;
        __syncthreads();                  // per-layer buffer: single barrier
        u64 off = 0ull;
        #pragma unroll
        for (int w2 = 0; w2 < 3; w2++){
            if (w2 < wid) off = add2(off, warp_s[l][w2]);
        }
        u64 bse = add2(off, fma2(c[7], NEG1, w));   // exclusive base

        #pragma unroll
        for (int k = 0; k < 8; k++){
            u64 cum = add2(bse, c[k]);
            float R, I; upk2(cum, R, I);
            float Ar = R*invc[k], Ai = I*invc[k];
            float m2 = fmaf(Ar, Ar, Ai*Ai) + 1e-12f;

            // E-table: bit-grid index (piecewise-log2), lerp exact in value
            unsigned bb = __float_as_uint(m2);
            int idx = (int)((bb - MBASE) >> MSH);
            idx = min(idx, MN-2);
            float fr = (float)(bb & MMASK) * (1.0f/262144.0f);
            float E0 = __ldg(&g_magtab[l][idx]);
            float E1 = __ldg(&g_magtab[l][idx+1]);
            float E  = fmaf(fr, E1 - E0, E0);

            // diamond angle u in [0,4)
            float ax = fabsf(Ar), ay = fabsf(Ai);
            float q  = ay * rcp_ap(ax + ay + 1e-30f);
            float u  = (Ar >= 0.f) ? q : 2.f - q;
            u        = (Ai >= 0.f) ? u : 4.f - u;
            float pf = u * ((float)PHN * 0.25f);
            float fl = floorf(pf);
            int   pp0 = ((int)fl) & (PHN-1);
            int   pp1 = (pp0 + 1)  & (PHN-1);
            float prf = pf - fl;
            // packed lerp of the normalized (gr,gi) table entries
            u64 gA = __ldg((const u64*)&g_phtab[l][pp0]);
            u64 gB = __ldg((const u64*)&g_phtab[l][pp1]);
            u64 gD = fma2(gA, NEG1, gB);               // gB - gA
            u64 g2 = fma2(pk2(prf, prf), gD, gA);

            float r = m2 * rsqrt_ap(m2) * E;           // sqrt(m2)*E
            z[k] = fma2(pk2(r, r), g2, z[k]);
        }
    }

    // decode needs only the real part
    float zr[8], zi_dummy;
    #pragma unroll
    for (int k = 0; k < 8; k++) upk2(z[k], zr[k], zi_dummy);
    float4* outp = (float4*)(g_zout + base);
    outp[2*t]   = make_float4(zr[0], zr[1], zr[2], zr[3]);
    outp[2*t+1] = make_float4(zr[4], zr[5], zr[6], zr[7]);
}

// ---------------------------------------------------------------------------
// Kernel C: decode as warp-tiled GEMV. Block = 32 s-values, 256 threads.
// ---------------------------------------------------------------------------
#define DBS 32
__global__ void __launch_bounds__(256) decode_kernel(
    const float* __restrict__ w1, const float* __restrict__ b1,
    const float* __restrict__ w2, const float* __restrict__ b2,
    float* __restrict__ out)
{
    __shared__ float sbuf[DD*HH];   // 32 KB: w1 tile [d][h], later partials [8][DBS][HH]
    int t = threadIdx.x;
    int w = t >> 5, lane = t & 31;
    int si = lane & 7;                   // s-quad: s = s_base + si*4 .. +3
    int hq = lane >> 3;                  // h-oct:  h = hq*8 .. +7

    int s_base = blockIdx.x * DBS;
    int b = s_base >> 10, s_in = s_base & (SS-1);
    const float* fp = g_zout + (size_t)b * DD * SS + (size_t)(w*32) * SS
                      + s_in + si*4;

    // prefetch first f chunk (4 d), then preload w1 (overlaps)
    float4 fbuf[2][4];
    #pragma unroll
    for (int dd = 0; dd < 4; dd++)
        fbuf[0][dd] = *(const float4*)(fp + (size_t)dd * SS);

    const float4* w1v = (const float4*)w1;
    float4* sv = (float4*)sbuf;
    #pragma unroll
    for (int i = 0; i < DD*HH/4/256; i++) sv[t + i*256] = w1v[t + i*256];
    __syncthreads();

    u64 acc[16];                         // [s-quad 4][h-pair 4]
    #pragma unroll
    for (int h = 0; h < 16; h++) acc[h] = 0ull;

    #pragma unroll
    for (int ch = 0; ch < 8; ch++){
        if (ch < 7){
            #pragma unroll
            for (int dd = 0; dd < 4; dd++)
                fbuf[(ch+1)&1][dd] = *(const float4*)(fp + (size_t)((ch+1)*4+dd) * SS);
        }
        #pragma unroll
        for (int dd = 0; dd < 4; dd++){
            int d = ch*4 + dd;
            const float* wr = sbuf + (w*32 + d)*HH + hq*8;
            ulonglong2 wv0 = *(const ulonglong2*)(wr);       // h-pairs 0,1
            ulonglong2 wv1 = *(const ulonglong2*)(wr + 4);   // h-pairs 2,3
            float4 f4 = fbuf[ch&1][dd];
            u64 f0 = pk2(f4.x, f4.x), f1 = pk2(f4.y, f4.y);
            u64 f2_ = pk2(f4.z, f4.z), f3 = pk2(f4.w, f4.w);
            acc[0]  = fma2(f0, wv0.x, acc[0]);  acc[1]  = fma2(f0, wv0.y, acc[1]);
            acc[2]  = fma2(f0, wv1.x, acc[2]);  acc[3]  = fma2(f0, wv1.y, acc[3]);
            acc[4]  = fma2(f1, wv0.x, acc[4]);  acc[5]  = fma2(f1, wv0.y, acc[5]);
            acc[6]  = fma2(f1, wv1.x, acc[6]);  acc[7]  = fma2(f1, wv1.y, acc[7]);
            acc[8]  = fma2(f2_, wv0.x, acc[8]); acc[9]  = fma2(f2_, wv0.y, acc[9]);
            acc[10] = fma2(f2_, wv1.x, acc[10]);acc[11] = fma2(f2_, wv1.y, acc[11]);
            acc[12] = fma2(f3, wv0.x, acc[12]); acc[13] = fma2(f3, wv0.y, acc[13]);
            acc[14] = fma2(f3, wv1.x, acc[14]); acc[15] = fma2(f3, wv1.y, acc[15]);
        }
    }
    __syncthreads();   // done reading w1 tile; sbuf becomes partials [8][DBS][HH]

    #pragma unroll
    for (int s4 = 0; s4 < 4; s4++){
        float* pr = sbuf + (w*DBS + si*4 + s4)*HH + hq*8;
        *(ulonglong2*)(pr)     = make_ulonglong2(acc[s4*4+0], acc[s4*4+1]);
        *(ulonglong2*)(pr + 4) = make_ulonglong2(acc[s4*4+2], acc[s4*4+3]);
    }
    __syncthreads();

    // final: warp w handles 4 s-values; lane = hidden unit
    float bb1 = b1[lane], ww2 = w2[lane], bb2 = b2[0];
    #pragma unroll
    for (int si2 = w*4; si2 < w*4 + 4; si2++){
        float hsum = bb1;
        #pragma unroll
        for (int g = 0; g < 8; g++)
            hsum += sbuf[(g*DBS + si2)*HH + lane];
        float y = gelu_exact(hsum) * ww2;
        #pragma unroll
        for (int o = 16; o; o >>= 1) y += __shfl_down_sync(0xffffffffu, y, o);
        if (lane == 0) out[blockIdx.x * DBS + si2] = y + bb2;
    }
}

// ---------------------------------------------------------------------------
extern "C" void kernel_launch(void* const* d_in, const int* in_sizes, int n_in,
                              void* d_out, int out_size)
{
    const float* x     = (const float*)d_in[0];
    const float* er_w  = (const float*)d_in[1];
    const float* er_b  = (const float*)d_in[2];
    const float* ei_w  = (const float*)d_in[3];
    const float* ei_b  = (const float*)d_in[4];
    const float* pm_w1 = (const float*)d_in[5];
    const float* pm_b1 = (const float*)d_in[6];
    const float* pm_w2 = (const float*)d_in[7];
    const float* pm_b2 = (const float*)d_in[8];
    const float* pp_w1 = (const float*)d_in[9];
    const float* pp_b1 = (const float*)d_in[10];
    const float* pp_w2 = (const float*)d_in[11];
    const float* pp_b2 = (const float*)d_in[12];
    const float* mscal = (const float*)d_in[13];
    const float* op_w1 = (const float*)d_in[14];
    const float* op_b1 = (const float*)d_in[15];
    const float* op_w2 = (const float*)d_in[16];
    const float* op_b2 = (const float*)d_in[17];
    float* out = (float*)d_out;

    embed_tables_kernel<<<EMB_BLOCKS + TAB_BLOCKS, 256>>>(
        x, er_w, er_b, ei_w, ei_b,
        pm_w1, pm_b1, pm_w2, pm_b2, pp_w1, pp_b1, pp_w2, pp_b2, mscal);
    layers_kernel<<<BB*DD, NT>>>();
    decode_kernel<<<BB*SS/DBS, 256>>>(op_w1, op_b1, op_w2, op_b2, out);
}

// round 15
// speedup vs baseline: 1.0674x; 1.0219x over previous
#include <cuda_runtime.h>
#include <math.h>

#define BB 8
#define SS 1024
#define DD 256
#define HH 32
#define INF 64
#define LL 4

#define MN 1280                // magnitude table entries (bit-grid)
#define MBASE (76u << 23)      // float bits of 2^-51; 16 steps/octave
#define MSH 19
#define MMASK ((1u << MSH) - 1u)
#define PHN 1024               // phase table entries

typedef unsigned long long u64;

// scratch: z interleaved (r,i) in [B][D][S]; zout = real part after layers
__device__ float2 g_zri[BB*DD*SS];
__device__ float  g_zout[BB*DD*SS];
// lookup tables
__device__ float  g_magtab[LL][MN];      // E = exp(scale*delta), m2-bit grid
__device__ float2 g_phtab[LL][PHN];      // NORMALIZED pv_out(u)

__device__ __forceinline__ float gelu_exact(float v){
    return 0.5f * v * (1.0f + erff(v * 0.70710678118654752f));
}

// ---- f32x2 packed helpers (sm_100+) ----
__device__ __forceinline__ u64 pk2(float lo, float hi){
    u64 r; asm("mov.b64 %0, {%1, %2};" : "=l"(r) : "f"(lo), "f"(hi)); return r;
}
__device__ __forceinline__ void upk2(u64 v, float &lo, float &hi){
    asm("mov.b64 {%0, %1}, %2;" : "=f"(lo), "=f"(hi) : "l"(v));
}
__device__ __forceinline__ u64 fma2(u64 a, u64 b, u64 c){
    u64 r; asm("fma.rn.f32x2 %0, %1, %2, %3;" : "=l"(r) : "l"(a), "l"(b), "l"(c)); return r;
}
__device__ __forceinline__ u64 add2(u64 a, u64 b){
    u64 r; asm("add.rn.f32x2 %0, %1, %2;" : "=l"(r) : "l"(a), "l"(b)); return r;
}
__device__ __forceinline__ float rcp_ap(float x){
    float y; asm("rcp.approx.f32 %0, %1;" : "=f"(y) : "f"(x)); return y;
}
__device__ __forceinline__ float rsqrt_ap(float x){
    float y; asm("rsqrt.approx.f32 %0, %1;" : "=f"(y) : "f"(x)); return y;
}

// ---------------------------------------------------------------------------
// Fused Kernel A+T: blocks [0,512) do embed; rest build tables.
// ---------------------------------------------------------------------------
#define TS 16
#define XST 20
#define EMB_BLOCKS (BB*(SS/TS))          // 512
#define TAB_BLOCKS (LL*(MN+PHN)/8)       // 1152

__global__ void __launch_bounds__(256, 4) embed_tables_kernel(
    const float* __restrict__ x,
    const float* __restrict__ erw, const float* __restrict__ erb,
    const float* __restrict__ eiw, const float* __restrict__ eib,
    const float* __restrict__ pm_w1, const float* __restrict__ pm_b1,
    const float* __restrict__ pm_w2, const float* __restrict__ pm_b2,
    const float* __restrict__ pp_w1, const float* __restrict__ pp_b1,
    const float* __restrict__ pp_w2, const float* __restrict__ pp_b2,
    const float* __restrict__ mag_scale)
{
    if (blockIdx.x >= EMB_BLOCKS){
        // ---------------- table builder: warp per entry, lane = hidden j ----
        int wgid = (blockIdx.x - EMB_BLOCKS) * 8 + (threadIdx.x >> 5);
        int j    = threadIdx.x & 31;
        if (wgid < LL*MN){
            int l = wgid / MN, k = wgid % MN;
            unsigned bits = MBASE + ((unsigned)k << MSH);
            float m2 = __uint_as_float(bits);
            float lm = 0.5f * logf(m2);
            float h  = fmaf(pm_w1[l*HH+j], lm, pm_b1[l*HH+j]);
            float v  = gelu_exact(h) * pm_w2[l*HH+j];
            #pragma unroll
            for (int o = 16; o; o >>= 1) v += __shfl_down_sync(0xffffffffu, v, o);
            if (j == 0) g_magtab[l][k] = expf(mag_scale[l] * (v + pm_b2[l]));
            return;
        }
        wgid -= LL*MN;
        {
            int l = wgid / PHN, k = wgid % PHN;
            float uu = 4.0f * (float)k / (float)PHN;
            float xx, yy;
            if (uu < 1.f)      { xx = 1.f-uu; yy = uu;     }
            else if (uu < 2.f) { xx = 1.f-uu; yy = 2.f-uu; }
            else if (uu < 3.f) { xx = uu-3.f; yy = 2.f-uu; }
            else               { xx = uu-3.f; yy = uu-4.f; }
            float inv = rsqrtf(fmaf(xx,xx,yy*yy));
            float px = xx*inv, py = yy*inv;
            float h = fmaf(px, pp_w1[l*2*HH + j],
                      fmaf(py, pp_w1[l*2*HH + HH + j], pp_b1[l*HH+j]));
            float g = gelu_exact(h);
            float vr = g * pp_w2[(l*HH+j)*2];
            float vi = g * pp_w2[(l*HH+j)*2 + 1];
            #pragma unroll
            for (int o = 16; o; o >>= 1){
                vr += __shfl_down_sync(0xffffffffu, vr, o);
                vi += __shfl_down_sync(0xffffffffu, vi, o);
            }
            if (j == 0){
                vr += pp_b2[l*2]; vi += pp_b2[l*2+1];
                float n = sqrtf(fmaf(vr, vr, vi*vi));
                float innv = 1.0f / fmaxf(n, 1e-12f);
                g_phtab[l][k] = make_float2(vr*innv, vi*innv);   // normalized
            }
            return;
        }
    }

    // -------------------------------- embed ---------------------------------
    __shared__ float  xsh[INF*XST];       // [i][s], stride 20 (16B aligned rows)
    __shared__ float2 zsh[DD][TS+1];      // interleaved (r,i), padded rows

    int t = threadIdx.x;                  // thread t owns d = t
    int nb_per_b = SS / TS;               // 64
    int b  = blockIdx.x / nb_per_b;
    int s0 = (blockIdx.x % nb_per_b) * TS;

    const float* xp = x + (size_t)(b*SS + s0) * INF;
    for (int e = t; e < TS*INF; e += 256){
        int s = e >> 6, i = e & 63;
        xsh[i*XST + s] = xp[e];
    }
    __syncthreads();

    int d = t;
    float br = erb[d], bi = eib[d];
    u64 ar2[TS/2], ai2[TS/2];
    #pragma unroll
    for (int p = 0; p < TS/2; p++){ ar2[p] = pk2(br, br); ai2[p] = pk2(bi, bi); }

    // chunked weight batching: 8 chunks x 8 i; 16 independent LDGs up front
    for (int c = 0; c < 8; c++){
        float wrb[8], wib[8];
        #pragma unroll
        for (int i = 0; i < 8; i++){
            wrb[i] = erw[(c*8+i)*DD + d];
            wib[i] = eiw[(c*8+i)*DD + d];
        }
        #pragma unroll
        for (int i = 0; i < 8; i++){
            u64 wr2 = pk2(wrb[i], wrb[i]);
            u64 wi2 = pk2(wib[i], wib[i]);
            const ulonglong2* xr = (const ulonglong2*)(xsh + (c*8+i)*XST);
            #pragma unroll
            for (int q = 0; q < TS/4; q++){
                ulonglong2 xv = xr[q];         // broadcast LDS.128 = 2 s-pairs
                ar2[2*q]   = fma2(xv.x, wr2, ar2[2*q]);
                ai2[2*q]   = fma2(xv.x, wi2, ai2[2*q]);
                ar2[2*q+1] = fma2(xv.y, wr2, ar2[2*q+1]);
                ai2[2*q+1] = fma2(xv.y, wi2, ai2[2*q+1]);
            }
        }
    }

    // fp32 freq (no FP64 pipe)
    float freq = expf((float)d * (-9.210340371976184f / 256.0f));
    float sn, cs, sdl, cdl;
    sincosf((float)s0 * freq, &sn, &cs);
    sincosf(freq, &sdl, &cdl);
    #pragma unroll
    for (int p = 0; p < TS/2; p++){
        float a0, a1, q0, q1;
        upk2(ar2[p], a0, a1);
        upk2(ai2[p], q0, q1);
        zsh[d][2*p]   = make_float2(a0*cs - q0*sn, a0*sn + q0*cs);
        float cn = cs*cdl - sn*sdl;
        float sx = sn*cdl + cs*sdl;
        cs = cn; sn = sx;
        zsh[d][2*p+1] = make_float2(a1*cs - q1*sn, a1*sn + q1*cs);
        cn = cs*cdl - sn*sdl;
        sx = sn*cdl + cs*sdl;
        cs = cn; sn = sx;
    }
    __syncthreads();

    // coalesced writeout via staging: warp writes contiguous s-runs
    float2* outz = g_zri + (size_t)b * DD * SS;
    for (int idx = t; idx < DD*TS; idx += 256){
        int dd = idx >> 4;
        int sx = idx & (TS-1);
        outz[dd*SS + s0 + sx] = zsh[dd][sx];
    }
}

// ---------------------------------------------------------------------------
// Kernel B: 4 causal polarizing blocks. 128 threads x 8 elems, (r,i) packed
// as f32x2. Bit-indexed E-table kills log+exp (2 MUFU/elem).
// ---------------------------------------------------------------------------
#define NT 128
__global__ void __launch_bounds__(NT) layers_kernel()
{
    __shared__ u64 warp_s[LL][4];

    int t = threadIdx.x;
    size_t base = (size_t)blockIdx.x * SS;        // blockIdx = b*D + d
    const ulonglong2* zp = (const ulonglong2*)(g_zri + base);
    ulonglong2 p0 = zp[4*t+0], p1 = zp[4*t+1], p2 = zp[4*t+2], p3 = zp[4*t+3];
    u64 z[8] = { p0.x, p0.y, p1.x, p1.y, p2.x, p2.y, p3.x, p3.y };

    float invc[8];
    #pragma unroll
    for (int k = 0; k < 8; k++) invc[k] = 1.0f / (float)(t*8 + k + 1);

    int lane = t & 31, wid = t >> 5;
    const u64 NEG1 = pk2(-1.0f, -1.0f);

    #pragma unroll
    for (int l = 0; l < LL; l++){
        // ---- packed inclusive scan over 1024 (r,i) pairs ----
        u64 c[8];
        c[0] = z[0];
        #pragma unroll
        for (int k = 1; k < 8; k++) c[k] = add2(c[k-1], z[k]);
        u64 w = c[7];
        #pragma unroll
        for (int o = 1; o < 32; o <<= 1){
            u64 u = __shfl_up_sync(0xffffffffu, w, o);
            if (lane >= o) w = add2(w, u);
        }
        if (lane == 31) warp_s[l][wid] = w;
        __syncthreads();                  // per-layer buffer: single barrier
        u64 off = 0ull;
        #pragma unroll
        for (int w2 = 0; w2 < 3; w2++){
            if (w2 < wid) off = add2(off, warp_s[l][w2]);
        }
        u64 bse = add2(off, fma2(c[7], NEG1, w));   // exclusive base

        #pragma unroll
        for (int k = 0; k < 8; k++){
            u64 cum = add2(bse, c[k]);
            float R, I; upk2(cum, R, I);
            float Ar = R*invc[k], Ai = I*invc[k];
            float m2 = fmaf(Ar, Ar, Ai*Ai) + 1e-12f;

            // E-table: bit-grid index (piecewise-log2), lerp exact in value
            unsigned bb = __float_as_uint(m2);
            int idx = (int)((bb - MBASE) >> MSH);
            idx = min(idx, MN-2);
            float fr = (float)(bb & MMASK) * (1.0f/524288.0f);
            float E0 = __ldg(&g_magtab[l][idx]);
            float E1 = __ldg(&g_magtab[l][idx+1]);
            float E  = fmaf(fr, E1 - E0, E0);

            // diamond angle u in [0,4)
            float ax = fabsf(Ar), ay = fabsf(Ai);
            float q  = ay * rcp_ap(ax + ay + 1e-30f);
            float u  = (Ar >= 0.f) ? q : 2.f - q;
            u        = (Ai >= 0.f) ? u : 4.f - u;
            float pf = u * ((float)PHN * 0.25f);
            float fl = floorf(pf);
            int   pp0 = ((int)fl) & (PHN-1);
            int   pp1 = (pp0 + 1)  & (PHN-1);
            float prf = pf - fl;
            // packed lerp of the normalized (gr,gi) table entries
            u64 gA = __ldg((const u64*)&g_phtab[l][pp0]);
            u64 gB = __ldg((const u64*)&g_phtab[l][pp1]);
            u64 gD = fma2(gA, NEG1, gB);               // gB - gA
            u64 g2 = fma2(pk2(prf, prf), gD, gA);

            float r = m2 * rsqrt_ap(m2) * E;           // sqrt(m2)*E
            z[k] = fma2(pk2(r, r), g2, z[k]);
        }
    }

    // decode needs only the real part
    float zr[8], zi_dummy;
    #pragma unroll
    for (int k = 0; k < 8; k++) upk2(z[k], zr[k], zi_dummy);
    float4* outp = (float4*)(g_zout + base);
    outp[2*t]   = make_float4(zr[0], zr[1], zr[2], zr[3]);
    outp[2*t+1] = make_float4(zr[4], zr[5], zr[6], zr[7]);
}

// ---------------------------------------------------------------------------
// Kernel C: decode as warp-tiled GEMV. Block = 32 s-values, 256 threads.
// ---------------------------------------------------------------------------
#define DBS 32
__global__ void __launch_bounds__(256) decode_kernel(
    const float* __restrict__ w1, const float* __restrict__ b1,
    const float* __restrict__ w2, const float* __restrict__ b2,
    float* __restrict__ out)
{
    __shared__ float sbuf[DD*HH];   // 32 KB: w1 tile [d][h], later partials [8][DBS][HH]
    int t = threadIdx.x;
    int w = t >> 5, lane = t & 31;
    int si = lane & 7;                   // s-quad: s = s_base + si*4 .. +3
    int hq = lane >> 3;                  // h-oct:  h = hq*8 .. +7

    int s_base = blockIdx.x * DBS;
    int b = s_base >> 10, s_in = s_base & (SS-1);
    const float* fp = g_zout + (size_t)b * DD * SS + (size_t)(w*32) * SS
                      + s_in + si*4;

    // prefetch first f chunk (4 d), then preload w1 (overlaps)
    float4 fbuf[2][4];
    #pragma unroll
    for (int dd = 0; dd < 4; dd++)
        fbuf[0][dd] = *(const float4*)(fp + (size_t)dd * SS);

    const float4* w1v = (const float4*)w1;
    float4* sv = (float4*)sbuf;
    #pragma unroll
    for (int i = 0; i < DD*HH/4/256; i++) sv[t + i*256] = w1v[t + i*256];
    __syncthreads();

    u64 acc[16];                         // [s-quad 4][h-pair 4]
    #pragma unroll
    for (int h = 0; h < 16; h++) acc[h] = 0ull;

    #pragma unroll
    for (int ch = 0; ch < 8; ch++){
        if (ch < 7){
            #pragma unroll
            for (int dd = 0; dd < 4; dd++)
                fbuf[(ch+1)&1][dd] = *(const float4*)(fp + (size_t)((ch+1)*4+dd) * SS);
        }
        #pragma unroll
        for (int dd = 0; dd < 4; dd++){
            int d = ch*4 + dd;
            const float* wr = sbuf + (w*32 + d)*HH + hq*8;
            ulonglong2 wv0 = *(const ulonglong2*)(wr);       // h-pairs 0,1
            ulonglong2 wv1 = *(const ulonglong2*)(wr + 4);   // h-pairs 2,3
            float4 f4 = fbuf[ch&1][dd];
            u64 f0 = pk2(f4.x, f4.x), f1 = pk2(f4.y, f4.y);
            u64 f2_ = pk2(f4.z, f4.z), f3 = pk2(f4.w, f4.w);
            acc[0]  = fma2(f0, wv0.x, acc[0]);  acc[1]  = fma2(f0, wv0.y, acc[1]);
            acc[2]  = fma2(f0, wv1.x, acc[2]);  acc[3]  = fma2(f0, wv1.y, acc[3]);
            acc[4]  = fma2(f1, wv0.x, acc[4]);  acc[5]  = fma2(f1, wv0.y, acc[5]);
            acc[6]  = fma2(f1, wv1.x, acc[6]);  acc[7]  = fma2(f1, wv1.y, acc[7]);
            acc[8]  = fma2(f2_, wv0.x, acc[8]); acc[9]  = fma2(f2_, wv0.y, acc[9]);
            acc[10] = fma2(f2_, wv1.x, acc[10]);acc[11] = fma2(f2_, wv1.y, acc[11]);
            acc[12] = fma2(f3, wv0.x, acc[12]); acc[13] = fma2(f3, wv0.y, acc[13]);
            acc[14] = fma2(f3, wv1.x, acc[14]); acc[15] = fma2(f3, wv1.y, acc[15]);
        }
    }
    __syncthreads();   // done reading w1 tile; sbuf becomes partials [8][DBS][HH]

    #pragma unroll
    for (int s4 = 0; s4 < 4; s4++){
        float* pr = sbuf + (w*DBS + si*4 + s4)*HH + hq*8;
        *(ulonglong2*)(pr)     = make_ulonglong2(acc[s4*4+0], acc[s4*4+1]);
        *(ulonglong2*)(pr + 4) = make_ulonglong2(acc[s4*4+2], acc[s4*4+3]);
    }
    __syncthreads();

    // final: warp w handles 4 s-values; lane = hidden unit
    float bb1 = b1[lane], ww2 = w2[lane], bb2 = b2[0];
    #pragma unroll
    for (int si2 = w*4; si2 < w*4 + 4; si2++){
        float hsum = bb1;
        #pragma unroll
        for (int g = 0; g < 8; g++)
            hsum += sbuf[(g*DBS + si2)*HH + lane];
        float y = gelu_exact(hsum) * ww2;
        #pragma unroll
        for (int o = 16; o; o >>= 1) y += __shfl_down_sync(0xffffffffu, y, o);
        if (lane == 0) out[blockIdx.x * DBS + si2] = y + bb2;
    }
}

// ---------------------------------------------------------------------------
extern "C" void kernel_launch(void* const* d_in, const int* in_sizes, int n_in,
                              void* d_out, int out_size)
{
    const float* x     = (const float*)d_in[0];
    const float* er_w  = (const float*)d_in[1];
    const float* er_b  = (const float*)d_in[2];
    const float* ei_w  = (const float*)d_in[3];
    const float* ei_b  = (const float*)d_in[4];
    const float* pm_w1 = (const float*)d_in[5];
    const float* pm_b1 = (const float*)d_in[6];
    const float* pm_w2 = (const float*)d_in[7];
    const float* pm_b2 = (const float*)d_in[8];
    const float* pp_w1 = (const float*)d_in[9];
    const float* pp_b1 = (const float*)d_in[10];
    const float* pp_w2 = (const float*)d_in[11];
    const float* pp_b2 = (const float*)d_in[12];
    const float* mscal = (const float*)d_in[13];
    const float* op_w1 = (const float*)d_in[14];
    const float* op_b1 = (const float*)d_in[15];
    const float* op_w2 = (const float*)d_in[16];
    const float* op_b2 = (const float*)d_in[17];
    float* out = (float*)d_out;

    embed_tables_kernel<<<EMB_BLOCKS + TAB_BLOCKS, 256>>>(
        x, er_w, er_b, ei_w, ei_b,
        pm_w1, pm_b1, pm_w2, pm_b2, pp_w1, pp_b1, pp_w2, pp_b2, mscal);
    layers_kernel<<<BB*DD, NT>>>();
    decode_kernel<<<BB*SS/DBS, 256>>>(op_w1, op_b1, op_w2, op_b2, out);
}

// round 16
// speedup vs baseline: 1.0738x; 1.0059x over previous
#include <cuda_runtime.h>
#include <math.h>

#define BB 8
#define SS 1024
#define DD 256
#define HH 32
#define INF 64
#define LL 4

#define MN 1280                // magnitude table entries (bit-grid)
#define MBASE (76u << 23)      // float bits of 2^-51; 16 steps/octave
#define MSH 19
#define MMASK ((1u << MSH) - 1u)
#define PHN 512                // phase table entries

typedef unsigned long long u64;

// scratch: z interleaved (r,i) in [B][D][S]; zout = real part after layers
__device__ float2 g_zri[BB*DD*SS];
__device__ float  g_zout[BB*DD*SS];
// lookup tables
__device__ float  g_magtab[LL][MN];      // E = exp(scale*delta), m2-bit grid
__device__ float2 g_phtab[LL][PHN];      // NORMALIZED pv_out(u)

__device__ __forceinline__ float gelu_exact(float v){
    return 0.5f * v * (1.0f + erff(v * 0.70710678118654752f));
}

// ---- f32x2 packed helpers (sm_100+) ----
__device__ __forceinline__ u64 pk2(float lo, float hi){
    u64 r; asm("mov.b64 %0, {%1, %2};" : "=l"(r) : "f"(lo), "f"(hi)); return r;
}
__device__ __forceinline__ void upk2(u64 v, float &lo, float &hi){
    asm("mov.b64 {%0, %1}, %2;" : "=f"(lo), "=f"(hi) : "l"(v));
}
__device__ __forceinline__ u64 fma2(u64 a, u64 b, u64 c){
    u64 r; asm("fma.rn.f32x2 %0, %1, %2, %3;" : "=l"(r) : "l"(a), "l"(b), "l"(c)); return r;
}
__device__ __forceinline__ u64 add2(u64 a, u64 b){
    u64 r; asm("add.rn.f32x2 %0, %1, %2;" : "=l"(r) : "l"(a), "l"(b)); return r;
}
__device__ __forceinline__ float rcp_ap(float x){
    float y; asm("rcp.approx.f32 %0, %1;" : "=f"(y) : "f"(x)); return y;
}
__device__ __forceinline__ float rsqrt_ap(float x){
    float y; asm("rsqrt.approx.f32 %0, %1;" : "=f"(y) : "f"(x)); return y;
}

// ---------------------------------------------------------------------------
// Fused Kernel A+T: blocks [0,512) do embed; rest build tables.
// ---------------------------------------------------------------------------
#define TS 16
#define XST 20
#define EMB_BLOCKS (BB*(SS/TS))          // 512
#define TAB_BLOCKS (LL*(MN+PHN)/8)       // 896

__global__ void __launch_bounds__(256, 4) embed_tables_kernel(
    const float* __restrict__ x,
    const float* __restrict__ erw, const float* __restrict__ erb,
    const float* __restrict__ eiw, const float* __restrict__ eib,
    const float* __restrict__ pm_w1, const float* __restrict__ pm_b1,
    const float* __restrict__ pm_w2, const float* __restrict__ pm_b2,
    const float* __restrict__ pp_w1, const float* __restrict__ pp_b1,
    const float* __restrict__ pp_w2, const float* __restrict__ pp_b2,
    const float* __restrict__ mag_scale)
{
    if (blockIdx.x >= EMB_BLOCKS){
        // ---------------- table builder: warp per entry, lane = hidden j ----
        int wgid = (blockIdx.x - EMB_BLOCKS) * 8 + (threadIdx.x >> 5);
        int j    = threadIdx.x & 31;
        if (wgid < LL*MN){
            int l = wgid / MN, k = wgid % MN;
            unsigned bits = MBASE + ((unsigned)k << MSH);
            float m2 = __uint_as_float(bits);
            float lm = 0.5f * logf(m2);
            float h  = fmaf(pm_w1[l*HH+j], lm, pm_b1[l*HH+j]);
            float v  = gelu_exact(h) * pm_w2[l*HH+j];
            #pragma unroll
            for (int o = 16; o; o >>= 1) v += __shfl_down_sync(0xffffffffu, v, o);
            if (j == 0) g_magtab[l][k] = expf(mag_scale[l] * (v + pm_b2[l]));
            return;
        }
        wgid -= LL*MN;
        {
            int l = wgid / PHN, k = wgid % PHN;
            float uu = 4.0f * (float)k / (float)PHN;
            float xx, yy;
            if (uu < 1.f)      { xx = 1.f-uu; yy = uu;     }
            else if (uu < 2.f) { xx = 1.f-uu; yy = 2.f-uu; }
            else if (uu < 3.f) { xx = uu-3.f; yy = 2.f-uu; }
            else               { xx = uu-3.f; yy = uu-4.f; }
            float inv = rsqrtf(fmaf(xx,xx,yy*yy));
            float px = xx*inv, py = yy*inv;
            float h = fmaf(px, pp_w1[l*2*HH + j],
                      fmaf(py, pp_w1[l*2*HH + HH + j], pp_b1[l*HH+j]));
            float g = gelu_exact(h);
            float vr = g * pp_w2[(l*HH+j)*2];
            float vi = g * pp_w2[(l*HH+j)*2 + 1];
            #pragma unroll
            for (int o = 16; o; o >>= 1){
                vr += __shfl_down_sync(0xffffffffu, vr, o);
                vi += __shfl_down_sync(0xffffffffu, vi, o);
            }
            if (j == 0){
                vr += pp_b2[l*2]; vi += pp_b2[l*2+1];
                float n = sqrtf(fmaf(vr, vr, vi*vi));
                float innv = 1.0f / fmaxf(n, 1e-12f);
                g_phtab[l][k] = make_float2(vr*innv, vi*innv);   // normalized
            }
            return;
        }
    }

    // -------------------------------- embed ---------------------------------
    __shared__ float  xsh[INF*XST];       // [i][s], stride 20 (16B aligned rows)
    __shared__ float2 zsh[DD][TS+1];      // interleaved (r,i), padded rows

    int t = threadIdx.x;                  // thread t owns d = t
    int nb_per_b = SS / TS;               // 64
    int b  = blockIdx.x / nb_per_b;
    int s0 = (blockIdx.x % nb_per_b) * TS;

    // x tile load: 1 LDG.128 per thread (4 consecutive i of one s), 4 STS
    {
        const float4* xp4 = (const float4*)(x + (size_t)(b*SS + s0) * INF);
        float4 v = xp4[t];                // thread t: s = t>>4, i = (t&15)*4
        int s = t >> 4, i0 = (t & 15) * 4;
        xsh[(i0+0)*XST + s] = v.x;
        xsh[(i0+1)*XST + s] = v.y;
        xsh[(i0+2)*XST + s] = v.z;
        xsh[(i0+3)*XST + s] = v.w;
    }
    __syncthreads();

    int d = t;
    float br = erb[d], bi = eib[d];
    u64 ar2[TS/2], ai2[TS/2];
    #pragma unroll
    for (int p = 0; p < TS/2; p++){ ar2[p] = pk2(br, br); ai2[p] = pk2(bi, bi); }

    // chunked weight batching: 8 chunks x 8 i; 16 independent LDGs up front
    for (int c = 0; c < 8; c++){
        float wrb[8], wib[8];
        #pragma unroll
        for (int i = 0; i < 8; i++){
            wrb[i] = erw[(c*8+i)*DD + d];
            wib[i] = eiw[(c*8+i)*DD + d];
        }
        #pragma unroll
        for (int i = 0; i < 8; i++){
            u64 wr2 = pk2(wrb[i], wrb[i]);
            u64 wi2 = pk2(wib[i], wib[i]);
            const ulonglong2* xr = (const ulonglong2*)(xsh + (c*8+i)*XST);
            #pragma unroll
            for (int q = 0; q < TS/4; q++){
                ulonglong2 xv = xr[q];         // broadcast LDS.128 = 2 s-pairs
                ar2[2*q]   = fma2(xv.x, wr2, ar2[2*q]);
                ai2[2*q]   = fma2(xv.x, wi2, ai2[2*q]);
                ar2[2*q+1] = fma2(xv.y, wr2, ar2[2*q+1]);
                ai2[2*q+1] = fma2(xv.y, wi2, ai2[2*q+1]);
            }
        }
    }

    // fp32 freq (no FP64 pipe)
    float freq = expf((float)d * (-9.210340371976184f / 256.0f));
    float sn, cs, sdl, cdl;
    sincosf((float)s0 * freq, &sn, &cs);
    sincosf(freq, &sdl, &cdl);
    #pragma unroll
    for (int p = 0; p < TS/2; p++){
        float a0, a1, q0, q1;
        upk2(ar2[p], a0, a1);
        upk2(ai2[p], q0, q1);
        zsh[d][2*p]   = make_float2(a0*cs - q0*sn, a0*sn + q0*cs);
        float cn = cs*cdl - sn*sdl;
        float sx = sn*cdl + cs*sdl;
        cs = cn; sn = sx;
        zsh[d][2*p+1] = make_float2(a1*cs - q1*sn, a1*sn + q1*cs);
        cn = cs*cdl - sn*sdl;
        sx = sn*cdl + cs*sdl;
        cs = cn; sn = sx;
    }
    __syncthreads();

    // coalesced writeout via staging: warp writes contiguous s-runs
    float2* outz = g_zri + (size_t)b * DD * SS;
    for (int idx = t; idx < DD*TS; idx += 256){
        int dd = idx >> 4;
        int sx = idx & (TS-1);
        outz[dd*SS + s0 + sx] = zsh[dd][sx];
    }
}

// ---------------------------------------------------------------------------
// Kernel B: 4 causal polarizing blocks. 128 threads x 8 elems, (r,i) packed
// as f32x2. PDL: prologue runs before embed finishes.
// ---------------------------------------------------------------------------
#define NT 128
__global__ void __launch_bounds__(NT) layers_kernel()
{
    __shared__ u64 warp_s[LL][4];

    int t = threadIdx.x;
    size_t base = (size_t)blockIdx.x * SS;        // blockIdx = b*D + d

    float invc[8];
    #pragma unroll
    for (int k = 0; k < 8; k++) invc[k] = 1.0f / (float)(t*8 + k + 1);

    int lane = t & 31, wid = t >> 5;
    const u64 NEG1 = pk2(-1.0f, -1.0f);

#if __CUDA_ARCH__ >= 900
    cudaGridDependencySynchronize();     // wait for embed+tables output
#endif

    const ulonglong2* zp = (const ulonglong2*)(g_zri + base);
    ulonglong2 p0 = zp[4*t+0], p1 = zp[4*t+1], p2 = zp[4*t+2], p3 = zp[4*t+3];
    u64 z[8] = { p0.x, p0.y, p1.x, p1.y, p2.x, p2.y, p3.x, p3.y };

    #pragma unroll
    for (int l = 0; l < LL; l++){
        // ---- packed inclusive scan over 1024 (r,i) pairs ----
        u64 c[8];
        c[0] = z[0];
        #pragma unroll
        for (int k = 1; k < 8; k++) c[k] = add2(c[k-1], z[k]);
        u64 w = c[7];
        #pragma unroll
        for (int o = 1; o < 32; o <<= 1){
            u64 u = __shfl_up_sync(0xffffffffu, w, o);
            if (lane >= o) w = add2(w, u);
        }
        if (lane == 31) warp_s[l][wid] = w;
        __syncthreads();                  // per-layer buffer: single barrier
        u64 off = 0ull;
        #pragma unroll
        for (int w2 = 0; w2 < 3; w2++){
            if (w2 < wid) off = add2(off, warp_s[l][w2]);
        }
        u64 bse = add2(off, fma2(c[7], NEG1, w));   // exclusive base

        #pragma unroll
        for (int k = 0; k < 8; k++){
            u64 cum = add2(bse, c[k]);
            float R, I; upk2(cum, R, I);
            float Ar = R*invc[k], Ai = I*invc[k];
            float m2 = fmaf(Ar, Ar, Ai*Ai) + 1e-12f;

            // E-table: bit-grid index (piecewise-log2), lerp exact in value
            unsigned bb = __float_as_uint(m2);
            int idx = (int)((bb - MBASE) >> MSH);
            idx = min(idx, MN-2);
            float fr = (float)(bb & MMASK) * (1.0f/524288.0f);
            float E0 = __ldg(&g_magtab[l][idx]);
            float E1 = __ldg(&g_magtab[l][idx+1]);
            float E  = fmaf(fr, E1 - E0, E0);

            // diamond angle u in [0,4)
            float ax = fabsf(Ar), ay = fabsf(Ai);
            float q  = ay * rcp_ap(ax + ay + 1e-30f);
            float u  = (Ar >= 0.f) ? q : 2.f - q;
            u        = (Ai >= 0.f) ? u : 4.f - u;
            float pf = u * ((float)PHN * 0.25f);
            float fl = floorf(pf);
            int   pp0 = ((int)fl) & (PHN-1);
            int   pp1 = (pp0 + 1)  & (PHN-1);
            float prf = pf - fl;
            // packed lerp of the normalized (gr,gi) table entries
            u64 gA = __ldg((const u64*)&g_phtab[l][pp0]);
            u64 gB = __ldg((const u64*)&g_phtab[l][pp1]);
            u64 gD = fma2(gA, NEG1, gB);               // gB - gA
            u64 g2 = fma2(pk2(prf, prf), gD, gA);

            float r = m2 * rsqrt_ap(m2) * E;           // sqrt(m2)*E
            z[k] = fma2(pk2(r, r), g2, z[k]);
        }
    }

    // decode needs only the real part
    float zr[8], zi_dummy;
    #pragma unroll
    for (int k = 0; k < 8; k++) upk2(z[k], zr[k], zi_dummy);
    float4* outp = (float4*)(g_zout + base);
    outp[2*t]   = make_float4(zr[0], zr[1], zr[2], zr[3]);
    outp[2*t+1] = make_float4(zr[4], zr[5], zr[6], zr[7]);
}

// ---------------------------------------------------------------------------
// Kernel C: decode as warp-tiled GEMV. Block = 32 s-values, 256 threads.
// PDL: w1 preload (32KB) runs before layers finishes.
// ---------------------------------------------------------------------------
#define DBS 32
__global__ void __launch_bounds__(256) decode_kernel(
    const float* __restrict__ w1, const float* __restrict__ b1,
    const float* __restrict__ w2, const float* __restrict__ b2,
    float* __restrict__ out)
{
    __shared__ float sbuf[DD*HH];   // 32 KB: w1 tile [d][h], later partials [8][DBS][HH]
    int t = threadIdx.x;
    int w = t >> 5, lane = t & 31;
    int si = lane & 7;                   // s-quad: s = s_base + si*4 .. +3
    int hq = lane >> 3;                  // h-oct:  h = hq*8 .. +7

    int s_base = blockIdx.x * DBS;
    int b = s_base >> 10, s_in = s_base & (SS-1);
    const float* fp = g_zout + (size_t)b * DD * SS + (size_t)(w*32) * SS
                      + s_in + si*4;

    // PDL prologue: w1 preload is independent of layers output
    const float4* w1v = (const float4*)w1;
    float4* sv = (float4*)sbuf;
    #pragma unroll
    for (int i = 0; i < DD*HH/4/256; i++) sv[t + i*256] = w1v[t + i*256];

#if __CUDA_ARCH__ >= 900
    cudaGridDependencySynchronize();     // wait for layers output
#endif
    __syncthreads();

    // prefetch first f chunk (4 d)
    float4 fbuf[2][4];
    #pragma unroll
    for (int dd = 0; dd < 4; dd++)
        fbuf[0][dd] = *(const float4*)(fp + (size_t)dd * SS);

    u64 acc[16];                         // [s-quad 4][h-pair 4]
    #pragma unroll
    for (int h = 0; h < 16; h++) acc[h] = 0ull;

    #pragma unroll
    for (int ch = 0; ch < 8; ch++){
        if (ch < 7){
            #pragma unroll
            for (int dd = 0; dd < 4; dd++)
                fbuf[(ch+1)&1][dd] = *(const float4*)(fp + (size_t)((ch+1)*4+dd) * SS);
        }
        #pragma unroll
        for (int dd = 0; dd < 4; dd++){
            int d = ch*4 + dd;
            const float* wr = sbuf + (w*32 + d)*HH + hq*8;
            ulonglong2 wv0 = *(const ulonglong2*)(wr);       // h-pairs 0,1
            ulonglong2 wv1 = *(const ulonglong2*)(wr + 4);   // h-pairs 2,3
            float4 f4 = fbuf[ch&1][dd];
            u64 f0 = pk2(f4.x, f4.x), f1 = pk2(f4.y, f4.y);
            u64 f2_ = pk2(f4.z, f4.z), f3 = pk2(f4.w, f4.w);
            acc[0]  = fma2(f0, wv0.x, acc[0]);  acc[1]  = fma2(f0, wv0.y, acc[1]);
            acc[2]  = fma2(f0, wv1.x, acc[2]);  acc[3]  = fma2(f0, wv1.y, acc[3]);
            acc[4]  = fma2(f1, wv0.x, acc[4]);  acc[5]  = fma2(f1, wv0.y, acc[5]);
            acc[6]  = fma2(f1, wv1.x, acc[6]);  acc[7]  = fma2(f1, wv1.y, acc[7]);
            acc[8]  = fma2(f2_, wv0.x, acc[8]); acc[9]  = fma2(f2_, wv0.y, acc[9]);
            acc[10] = fma2(f2_, wv1.x, acc[10]);acc[11] = fma2(f2_, wv1.y, acc[11]);
            acc[12] = fma2(f3, wv0.x, acc[12]); acc[13] = fma2(f3, wv0.y, acc[13]);
            acc[14] = fma2(f3, wv1.x, acc[14]); acc[15] = fma2(f3, wv1.y, acc[15]);
        }
    }
    __syncthreads();   // done reading w1 tile; sbuf becomes partials [8][DBS][HH]

    #pragma unroll
    for (int s4 = 0; s4 < 4; s4++){
        float* pr = sbuf + (w*DBS + si*4 + s4)*HH + hq*8;
        *(ulonglong2*)(pr)     = make_ulonglong2(acc[s4*4+0], acc[s4*4+1]);
        *(ulonglong2*)(pr + 4) = make_ulonglong2(acc[s4*4+2], acc[s4*4+3]);
    }
    __syncthreads();

    // final: warp w handles 4 s-values; lane = hidden unit
    float bb1 = b1[lane], ww2 = w2[lane], bb2 = b2[0];
    #pragma unroll
    for (int si2 = w*4; si2 < w*4 + 4; si2++){
        float hsum = bb1;
        #pragma unroll
        for (int g = 0; g < 8; g++)
            hsum += sbuf[(g*DBS + si2)*HH + lane];
        float y = gelu_exact(hsum) * ww2;
        #pragma unroll
        for (int o = 16; o; o >>= 1) y += __shfl_down_sync(0xffffffffu, y, o);
        if (lane == 0) out[blockIdx.x * DBS + si2] = y + bb2;
    }
}

// ---------------------------------------------------------------------------
extern "C" void kernel_launch(void* const* d_in, const int* in_sizes, int n_in,
                              void* d_out, int out_size)
{
    const float* x     = (const float*)d_in[0];
    const float* er_w  = (const float*)d_in[1];
    const float* er_b  = (const float*)d_in[2];
    const float* ei_w  = (const float*)d_in[3];
    const float* ei_b  = (const float*)d_in[4];
    const float* pm_w1 = (const float*)d_in[5];
    const float* pm_b1 = (const float*)d_in[6];
    const float* pm_w2 = (const float*)d_in[7];
    const float* pm_b2 = (const float*)d_in[8];
    const float* pp_w1 = (const float*)d_in[9];
    const float* pp_b1 = (const float*)d_in[10];
    const float* pp_w2 = (const float*)d_in[11];
    const float* pp_b2 = (const float*)d_in[12];
    const float* mscal = (const float*)d_in[13];
    const float* op_w1 = (const float*)d_in[14];
    const float* op_b1 = (const float*)d_in[15];
    const float* op_w2 = (const float*)d_in[16];
    const float* op_b2 = (const float*)d_in[17];
    float* out = (float*)d_out;

    embed_tables_kernel<<<EMB_BLOCKS + TAB_BLOCKS, 256>>>(
        x, er_w, er_b, ei_w, ei_b,
        pm_w1, pm_b1, pm_w2, pm_b2, pp_w1, pp_b1, pp_w2, pp_b2, mscal);

    // layers with PDL: prologue overlaps embed tail
    {
        cudaLaunchConfig_t cfg = {};
        cfg.gridDim  = dim3(BB*DD, 1, 1);
        cfg.blockDim = dim3(NT, 1, 1);
        cudaLaunchAttribute attrs[1];
        attrs[0].id = cudaLaunchAttributeProgrammaticStreamSerialization;
        attrs[0].val.programmaticStreamSerializationAllowed = 1;
        cfg.attrs = attrs;
        cfg.numAttrs = 1;
        cudaLaunchKernelEx(&cfg, layers_kernel);
    }

    // decode with PDL: w1 preload overlaps layers tail
    {
        cudaLaunchConfig_t cfg = {};
        cfg.gridDim  = dim3(BB*SS/DBS, 1, 1);
        cfg.blockDim = dim3(256, 1, 1);
        cudaLaunchAttribute attrs[1];
        attrs[0].id = cudaLaunchAttributeProgrammaticStreamSerialization;
        attrs[0].val.programmaticStreamSerializationAllowed = 1;
        cfg.attrs = attrs;
        cfg.numAttrs = 1;
        cudaLaunchKernelEx(&cfg, decode_kernel, op_w1, op_b1, op_w2, op_b2, out);
    }
}